// round 16
// baseline (speedup 1.0000x reference)
#include <cuda_runtime.h>
#include <cuda_bf16.h>
#include <math.h>

// ---------------------------------------------------------------------------
// DiscriptorMatchLoss — sparse cosine loss, bucket hash + normalized bf16.
//   mask[i,j,n,m] = ||denorm(ps[i,n]) - denorm(pd[i,j,m])||^2 <= 64
//   out = sum_mask (1 - cos(f[j,n], f[i,m])) / max(count,1)
//   K1: bucket-bin dst points (float4 buckets: x, y, idx).
//   K2: [match: 1 thread per (src pt, candidate cell)] || [normalize rows
//       -> bf16] — block-partitioned, independent halves.
//   K3: bf16 dots (16 pairs/warp, 2 lanes/pair, 4 accumulators), block
//       reduce, bucket reset, ticket finalize.
// ---------------------------------------------------------------------------

#define MAXC      2048
#define MAXIJ     16
#define CAP       16             // lambda~1.7 => P(overflow) ~ 1e-12/cell
#define MAX_PAIRS (1 << 20)
#define MAXR      16384
#define MAXD      256
#define RAD       8.0f
#define RAD2      64.0f
#define NTHR      256
#define DOT_GRID  1184

__device__ double        g_sum;                  // reset by k_dot ticket winner
__device__ int           g_npairs;               // reset by k_dot ticket winner
__device__ unsigned      g_done;
__device__ int           g_ccnt[MAXIJ * MAXC];   // reset in k_dot
__device__ float4        g_cbkt[MAXIJ * MAXC * CAP]; // {x, y, idx_as_float, -}
__device__ unsigned      g_pairs[MAX_PAIRS];
__device__ __nv_bfloat16 g_fbn[MAXR * MAXD];     // normalized bf16 features

__device__ __forceinline__ void grid_shape(int W, int H, int& s, int& ncx, int& ncy) {
    s = 4;
    ncx = ((W - 1) >> s) + 1; ncy = ((H - 1) >> s) + 1;
    while (ncx * ncy > MAXC) { s++; ncx = ((W - 1) >> s) + 1; ncy = ((H - 1) >> s) + 1; }
}

__device__ __forceinline__ float bfdot2(unsigned a, unsigned b, float acc) {
    float a0 = __uint_as_float(a << 16);
    float a1 = __uint_as_float(a & 0xffff0000u);
    float b0 = __uint_as_float(b << 16);
    float b1 = __uint_as_float(b & 0xffff0000u);
    return fmaf(a0, b0, fmaf(a1, b1, acc));
}

__device__ __forceinline__ unsigned pack_bf2(float x, float y) {
    __nv_bfloat162 h = __floats2bfloat162_rn(x, y);
    return *(unsigned*)&h;
}

// ---------------- K1: bucket-bin dst points --------------------------------
__global__ void __launch_bounds__(128)
k_bin(const float* __restrict__ pd,
      const int* __restrict__ hp,
      const int* __restrict__ wp,
      int B, int N) {
    int t = blockIdx.x * 128 + threadIdx.x;
    int total = B * B * N;
    if (t >= total) return;
    float2 q = ((const float2*)pd)[t];          // issue data load first
    int W = wp[0], H = hp[0];
    int ij = t / N;
    int s, ncx, ncy; grid_shape(W, H, s, ncx, ncy);
    float inv_c = 1.0f / (float)(1 << s);
    float sx = 0.5f * (float)(W - 1), sy = 0.5f * (float)(H - 1);
    float x = (q.x + 1.0f) * sx, y = (q.y + 1.0f) * sy;
    int cx = min(ncx - 1, max(0, (int)(x * inv_c)));
    int cy = min(ncy - 1, max(0, (int)(y * inv_c)));
    int cell = ij * MAXC + cy * ncx + cx;
    int slot = atomicAdd(&g_ccnt[cell], 1);
    if (slot < CAP)
        g_cbkt[cell * CAP + slot] =
            make_float4(x, y, __int_as_float(t % N), 0.f);
}

// ---------------- K2: match || normalize (block-partitioned) ---------------
__global__ void __launch_bounds__(NTHR)
k_mn(const float* __restrict__ f,
     const float* __restrict__ ps,
     const int* __restrict__ hp,
     const int* __restrict__ wp,
     int B, int N, int D, int rows, int matchBlocks) {
    const int tid  = threadIdx.x;
    const int lane = tid & 31;

    if ((int)blockIdx.x >= matchBlocks) {
        // ---- normalize: one warp per feature row ----
        int w = ((int)blockIdx.x - matchBlocks) * 8 + (tid >> 5);
        if (w >= rows) return;
        const float4* row = (const float4*)(f + (size_t)w * D);
        uint2* outr = (uint2*)(g_fbn + (size_t)w * D);
        const int D4 = D >> 2;
        if (D4 == 64) {
            float4 v0 = row[lane];
            float4 v1 = row[lane + 32];
            float ss = v0.x*v0.x + v0.y*v0.y + v0.z*v0.z + v0.w*v0.w
                     + v1.x*v1.x + v1.y*v1.y + v1.z*v1.z + v1.w*v1.w;
            #pragma unroll
            for (int o = 16; o; o >>= 1) ss += __shfl_xor_sync(0xffffffffu, ss, o);
            float invn = rsqrtf(ss);
            uint2 o0, o1;
            o0.x = pack_bf2(v0.x * invn, v0.y * invn);
            o0.y = pack_bf2(v0.z * invn, v0.w * invn);
            o1.x = pack_bf2(v1.x * invn, v1.y * invn);
            o1.y = pack_bf2(v1.z * invn, v1.w * invn);
            outr[lane]      = o0;
            outr[lane + 32] = o1;
        } else {
            float ss = 0.f;
            for (int d = lane; d < D4; d += 32) {
                float4 vv = row[d];
                ss += vv.x*vv.x + vv.y*vv.y + vv.z*vv.z + vv.w*vv.w;
            }
            #pragma unroll
            for (int o = 16; o; o >>= 1) ss += __shfl_xor_sync(0xffffffffu, ss, o);
            float invn = rsqrtf(ss);
            for (int d = lane; d < D4; d += 32) {
                float4 vv = row[d];
                uint2 o2;
                o2.x = pack_bf2(vv.x * invn, vv.y * invn);
                o2.y = pack_bf2(vv.z * invn, vv.w * invn);
                outr[d] = o2;
            }
        }
        return;
    }

    // ---- match: 1 thread per (src point, candidate cell) ----
    const int t4 = blockIdx.x * NTHR + tid;
    const int total = B * B * N;
    unsigned hits[8];
    int hc = 0;
    const int t = t4 >> 2;
    const int c = t4 & 3;

    if (t < total) {
        int n  = t % N;
        int ij = t / N;
        int i  = ij / B;
        float2 q = ((const float2*)ps)[(size_t)i * N + n];   // head load 1
        int W = wp[0], H = hp[0];                             // head load 2 (uniform)
        int s, ncx, ncy; grid_shape(W, H, s, ncx, ncy);
        float inv_c = 1.0f / (float)(1 << s);
        float sx = 0.5f * (float)(W - 1), sy = 0.5f * (float)(H - 1);

        float x = (q.x + 1.0f) * sx, y = (q.y + 1.0f) * sy;
        int cx0 = max(0, (int)floorf((x - RAD) * inv_c));
        int cx1 = min(ncx - 1, (int)floorf((x + RAD) * inv_c));
        int cy0 = max(0, (int)floorf((y - RAD) * inv_c));
        int cy1 = min(ncy - 1, (int)floorf((y + RAD) * inv_c));

        int nwx = cx1 - cx0 + 1;
        int nwy = cy1 - cy0 + 1;
        int wx = c & 1, wy = c >> 1;
        if (wx < nwx && wy < nwy) {
            int cell = ij * MAXC + (cy0 + wy) * ncx + (cx0 + wx);
            int cnt = g_ccnt[cell];
            if (cnt > CAP) cnt = CAP;
            const float4* cb = g_cbkt + (size_t)cell * CAP;
            for (int k = 0; k < cnt; k++) {
                float4 p = cb[k];
                float dx = p.x - x, dy = p.y - y;
                if (dx * dx + dy * dy <= RAD2) {
                    unsigned pk = ((unsigned)ij << 24) |
                                  ((unsigned)n << 12) |
                                  (unsigned)__float_as_int(p.z);
                    if (hc < 8) hits[hc++] = pk;
                    else {
                        int pos = atomicAdd(&g_npairs, 1);
                        if (pos < MAX_PAIRS) g_pairs[pos] = pk;
                    }
                }
            }
        }
    }

    // warp-aggregated append
    int pre = hc;
    #pragma unroll
    for (int o = 1; o < 32; o <<= 1) {
        int v = __shfl_up_sync(0xffffffffu, pre, o);
        if (lane >= o) pre += v;
    }
    int tot  = __shfl_sync(0xffffffffu, pre, 31);
    int excl = pre - hc;
    if (tot > 0) {
        int bpos = 0;
        if (lane == 31) bpos = atomicAdd(&g_npairs, tot);
        bpos = __shfl_sync(0xffffffffu, bpos, 31);
        for (int k = 0; k < hc; k++) {
            int pos = bpos + excl + k;
            if (pos < MAX_PAIRS) g_pairs[pos] = hits[k];
        }
    }
}

// ---------------- K3: bf16 dots, 16 pairs/warp + finalize ------------------
__global__ void __launch_bounds__(NTHR)
k_dot(float* __restrict__ out, int B, int N, int D) {
    __shared__ float s_red[8];
    __shared__ unsigned s_ticket;
    const int tid   = threadIdx.x;
    const int lane  = tid & 31;
    const int wid   = tid >> 5;
    const int sub   = lane >> 1;     // 16 pairs per warp
    const int sl    = lane & 1;      // 2 lanes per pair
    const int gw    = (blockIdx.x * NTHR + tid) >> 5;
    const int nwarp = (gridDim.x * NTHR) >> 5;

    int np = g_npairs;
    if (np > MAX_PAIRS) np = MAX_PAIRS;
    const int D8 = D >> 3;           // uint4 (8 bf16) per row

    float lsum = 0.f;
    for (int p0 = gw * 16; p0 < np; p0 += nwarp * 16) {
        int p = p0 + sub;
        bool valid = p < np;
        float d0 = 0.f, d1 = 0.f, d2 = 0.f, d3 = 0.f;
        if (valid) {
            unsigned pk = g_pairs[p];            // hoisted key load
            int ij = pk >> 24;
            int n  = (pk >> 12) & 0xFFF;
            int m  = pk & 0xFFF;
            int i  = ij / B;
            int j  = ij - i * B;
            const uint4* fa = (const uint4*)(g_fbn + (size_t)(j * N + n) * D);
            const uint4* fb = (const uint4*)(g_fbn + (size_t)(i * N + m) * D);
            if (D8 == 32) {
                #pragma unroll
                for (int it = 0; it < 16; it++) {
                    int d = sl + it * 2;
                    uint4 a = fa[d], b = fb[d];
                    d0 = bfdot2(a.x, b.x, d0);   // 4 independent chains
                    d1 = bfdot2(a.y, b.y, d1);
                    d2 = bfdot2(a.z, b.z, d2);
                    d3 = bfdot2(a.w, b.w, d3);
                }
            } else {
                for (int d = sl; d < D8; d += 2) {
                    uint4 a = fa[d], b = fb[d];
                    d0 = bfdot2(a.x, b.x, d0);
                    d1 = bfdot2(a.y, b.y, d1);
                    d2 = bfdot2(a.z, b.z, d2);
                    d3 = bfdot2(a.w, b.w, d3);
                }
            }
        }
        float dot = (d0 + d1) + (d2 + d3);
        dot += __shfl_xor_sync(0xffffffffu, dot, 1);
        if (valid && sl == 0) lsum += 1.0f - dot;
    }
    #pragma unroll
    for (int o = 16; o; o >>= 1) lsum += __shfl_xor_sync(0xffffffffu, lsum, o);
    if (lane == 0) s_red[wid] = lsum;
    __syncthreads();
    if (wid == 0) {
        float v = (lane < 8) ? s_red[lane] : 0.f;
        #pragma unroll
        for (int o = 4; o; o >>= 1) v += __shfl_xor_sync(0xffffffffu, v, o);
        if (lane == 0 && v != 0.f) atomicAdd(&g_sum, (double)v);
    }

    // distributed reset of bucket counts for next graph replay
    {
        int ncnt = B * B * MAXC;
        for (int c = blockIdx.x * NTHR + tid; c < ncnt; c += gridDim.x * NTHR)
            g_ccnt[c] = 0;
    }

    __threadfence();
    __syncthreads();
    if (tid == 0) s_ticket = atomicAdd(&g_done, 1u);
    __syncthreads();
    if (s_ticket == gridDim.x - 1 && tid == 0) {
        __threadfence();
        double sv = atomicAdd(&g_sum, 0.0);
        int c = np < 1 ? 1 : np;
        out[0] = (float)(sv / (double)c);
        g_sum = 0.0;
        g_npairs = 0;
        g_done = 0u;
    }
}

extern "C" void kernel_launch(void* const* d_in, const int* in_sizes, int n_in,
                              void* d_out, int out_size) {
    const float* features = (const float*)d_in[0];
    const float* pts_src  = (const float*)d_in[1];
    const float* pts_dst  = (const float*)d_in[2];
    const int* hp = (const int*)d_in[4];
    const int* wp = (const int*)d_in[5];
    float* out = (float*)d_out;

    int B = in_sizes[2] / in_sizes[1];
    int N = in_sizes[1] / (2 * B);
    int D = in_sizes[0] / (B * N);
    int rows = B * N;

    int binBlocks   = (B * B * N + 127) / 128;
    int matchBlocks = (B * B * N * 4 + NTHR - 1) / NTHR;
    int normBlocks  = (rows + 7) / 8;
    k_bin<<<binBlocks, 128>>>(pts_dst, hp, wp, B, N);
    k_mn<<<matchBlocks + normBlocks, NTHR>>>(features, pts_src, hp, wp,
                                             B, N, D, rows, matchBlocks);
    k_dot<<<DOT_GRID, NTHR>>>(out, B, N, D);
    (void)n_in; (void)out_size;
}

// round 17
// speedup vs baseline: 1.4885x; 1.4885x over previous
#include <cuda_runtime.h>
#include <cuda_bf16.h>
#include <math.h>

// ---------------------------------------------------------------------------
// DiscriptorMatchLoss — sparse cosine loss, bucket hash + normalized bf16.
//   mask[i,j,n,m] = ||denorm(ps[i,n]) - denorm(pd[i,j,m])||^2 <= 64
//   out = sum_mask (1 - cos(f[j,n], f[i,m])) / max(count,1)
//   K1: bucket-bin dst points (float4 buckets: x, y, idx).
//   K2: [match: 1 thread per (src pt, candidate cell)] || [normalize rows
//       -> bf16] — block-partitioned, independent halves.
//   K3: bf16 dots (8 pairs/warp, 4 lanes/pair, 4 accumulators, next-key
//       prefetch), block reduce, bucket reset, ticket finalize.
// (R15 configuration restored; R16's 16-pairs/warp + CAP=16 reverted.)
// ---------------------------------------------------------------------------

#define MAXC      2048
#define MAXIJ     16
#define CAP       32
#define MAX_PAIRS (1 << 20)
#define MAXR      16384
#define MAXD      256
#define RAD       8.0f
#define RAD2      64.0f
#define NTHR      256
#define DOT_GRID  1184

__device__ double        g_sum;                  // reset by k_dot ticket winner
__device__ int           g_npairs;               // reset by k_dot ticket winner
__device__ unsigned      g_done;
__device__ int           g_ccnt[MAXIJ * MAXC];   // reset in k_dot
__device__ float4        g_cbkt[MAXIJ * MAXC * CAP]; // {x, y, idx_as_float, -}
__device__ unsigned      g_pairs[MAX_PAIRS];
__device__ __nv_bfloat16 g_fbn[MAXR * MAXD];     // normalized bf16 features

__device__ __forceinline__ void grid_shape(int W, int H, int& s, int& ncx, int& ncy) {
    s = 4;
    ncx = ((W - 1) >> s) + 1; ncy = ((H - 1) >> s) + 1;
    while (ncx * ncy > MAXC) { s++; ncx = ((W - 1) >> s) + 1; ncy = ((H - 1) >> s) + 1; }
}

__device__ __forceinline__ float bfdot2(unsigned a, unsigned b, float acc) {
    float a0 = __uint_as_float(a << 16);
    float a1 = __uint_as_float(a & 0xffff0000u);
    float b0 = __uint_as_float(b << 16);
    float b1 = __uint_as_float(b & 0xffff0000u);
    return fmaf(a0, b0, fmaf(a1, b1, acc));
}

__device__ __forceinline__ unsigned pack_bf2(float x, float y) {
    __nv_bfloat162 h = __floats2bfloat162_rn(x, y);
    return *(unsigned*)&h;
}

// ---------------- K1: bucket-bin dst points --------------------------------
__global__ void __launch_bounds__(NTHR)
k_bin(const float* __restrict__ pd,
      const int* __restrict__ hp,
      const int* __restrict__ wp,
      int B, int N) {
    int t = blockIdx.x * NTHR + threadIdx.x;
    int total = B * B * N;
    if (t >= total) return;
    float2 q = ((const float2*)pd)[t];          // issue data load first
    int W = wp[0], H = hp[0];
    int ij = t / N;
    int s, ncx, ncy; grid_shape(W, H, s, ncx, ncy);
    float inv_c = 1.0f / (float)(1 << s);
    float sx = 0.5f * (float)(W - 1), sy = 0.5f * (float)(H - 1);
    float x = (q.x + 1.0f) * sx, y = (q.y + 1.0f) * sy;
    int cx = min(ncx - 1, max(0, (int)(x * inv_c)));
    int cy = min(ncy - 1, max(0, (int)(y * inv_c)));
    int cell = ij * MAXC + cy * ncx + cx;
    int slot = atomicAdd(&g_ccnt[cell], 1);
    if (slot < CAP)
        g_cbkt[cell * CAP + slot] =
            make_float4(x, y, __int_as_float(t % N), 0.f);
}

// ---------------- K2: match || normalize (block-partitioned) ---------------
__global__ void __launch_bounds__(NTHR)
k_mn(const float* __restrict__ f,
     const float* __restrict__ ps,
     const int* __restrict__ hp,
     const int* __restrict__ wp,
     int B, int N, int D, int rows, int matchBlocks) {
    const int tid  = threadIdx.x;
    const int lane = tid & 31;

    if ((int)blockIdx.x >= matchBlocks) {
        // ---- normalize: one warp per feature row ----
        int w = ((int)blockIdx.x - matchBlocks) * 8 + (tid >> 5);
        if (w >= rows) return;
        const float4* row = (const float4*)(f + (size_t)w * D);
        uint2* outr = (uint2*)(g_fbn + (size_t)w * D);
        const int D4 = D >> 2;
        if (D4 == 64) {
            float4 v0 = row[lane];
            float4 v1 = row[lane + 32];
            float ss = v0.x*v0.x + v0.y*v0.y + v0.z*v0.z + v0.w*v0.w
                     + v1.x*v1.x + v1.y*v1.y + v1.z*v1.z + v1.w*v1.w;
            #pragma unroll
            for (int o = 16; o; o >>= 1) ss += __shfl_xor_sync(0xffffffffu, ss, o);
            float invn = rsqrtf(ss);
            uint2 o0, o1;
            o0.x = pack_bf2(v0.x * invn, v0.y * invn);
            o0.y = pack_bf2(v0.z * invn, v0.w * invn);
            o1.x = pack_bf2(v1.x * invn, v1.y * invn);
            o1.y = pack_bf2(v1.z * invn, v1.w * invn);
            outr[lane]      = o0;
            outr[lane + 32] = o1;
        } else {
            float ss = 0.f;
            for (int d = lane; d < D4; d += 32) {
                float4 vv = row[d];
                ss += vv.x*vv.x + vv.y*vv.y + vv.z*vv.z + vv.w*vv.w;
            }
            #pragma unroll
            for (int o = 16; o; o >>= 1) ss += __shfl_xor_sync(0xffffffffu, ss, o);
            float invn = rsqrtf(ss);
            for (int d = lane; d < D4; d += 32) {
                float4 vv = row[d];
                uint2 o2;
                o2.x = pack_bf2(vv.x * invn, vv.y * invn);
                o2.y = pack_bf2(vv.z * invn, vv.w * invn);
                outr[d] = o2;
            }
        }
        return;
    }

    // ---- match: 1 thread per (src point, candidate cell) ----
    const int t4 = blockIdx.x * NTHR + tid;
    const int total = B * B * N;
    unsigned hits[8];
    int hc = 0;
    const int t = t4 >> 2;
    const int c = t4 & 3;

    if (t < total) {
        int n  = t % N;
        int ij = t / N;
        int i  = ij / B;
        float2 q = ((const float2*)ps)[(size_t)i * N + n];   // head load 1
        int W = wp[0], H = hp[0];                             // head load 2 (uniform)
        int s, ncx, ncy; grid_shape(W, H, s, ncx, ncy);
        float inv_c = 1.0f / (float)(1 << s);
        float sx = 0.5f * (float)(W - 1), sy = 0.5f * (float)(H - 1);

        float x = (q.x + 1.0f) * sx, y = (q.y + 1.0f) * sy;
        int cx0 = max(0, (int)floorf((x - RAD) * inv_c));
        int cx1 = min(ncx - 1, (int)floorf((x + RAD) * inv_c));
        int cy0 = max(0, (int)floorf((y - RAD) * inv_c));
        int cy1 = min(ncy - 1, (int)floorf((y + RAD) * inv_c));

        int nwx = cx1 - cx0 + 1;
        int nwy = cy1 - cy0 + 1;
        int wx = c & 1, wy = c >> 1;
        if (wx < nwx && wy < nwy) {
            int cell = ij * MAXC + (cy0 + wy) * ncx + (cx0 + wx);
            int cnt = g_ccnt[cell];
            if (cnt > CAP) cnt = CAP;
            const float4* cb = g_cbkt + (size_t)cell * CAP;
            for (int k = 0; k < cnt; k++) {
                float4 p = cb[k];
                float dx = p.x - x, dy = p.y - y;
                if (dx * dx + dy * dy <= RAD2) {
                    unsigned pk = ((unsigned)ij << 24) |
                                  ((unsigned)n << 12) |
                                  (unsigned)__float_as_int(p.z);
                    if (hc < 8) hits[hc++] = pk;
                    else {
                        int pos = atomicAdd(&g_npairs, 1);
                        if (pos < MAX_PAIRS) g_pairs[pos] = pk;
                    }
                }
            }
        }
    }

    // warp-aggregated append
    int pre = hc;
    #pragma unroll
    for (int o = 1; o < 32; o <<= 1) {
        int v = __shfl_up_sync(0xffffffffu, pre, o);
        if (lane >= o) pre += v;
    }
    int tot  = __shfl_sync(0xffffffffu, pre, 31);
    int excl = pre - hc;
    if (tot > 0) {
        int bpos = 0;
        if (lane == 31) bpos = atomicAdd(&g_npairs, tot);
        bpos = __shfl_sync(0xffffffffu, bpos, 31);
        for (int k = 0; k < hc; k++) {
            int pos = bpos + excl + k;
            if (pos < MAX_PAIRS) g_pairs[pos] = hits[k];
        }
    }
}

// ---------------- K3: bf16 dots, 4 accumulators + key prefetch -------------
__global__ void __launch_bounds__(NTHR)
k_dot(float* __restrict__ out, int B, int N, int D) {
    __shared__ float s_red[8];
    __shared__ unsigned s_ticket;
    const int tid   = threadIdx.x;
    const int lane  = tid & 31;
    const int wid   = tid >> 5;
    const int sub   = lane >> 2;     // 8 pairs per warp
    const int sl    = lane & 3;      // 4 lanes per pair
    const int gw    = (blockIdx.x * NTHR + tid) >> 5;
    const int nwarp = (gridDim.x * NTHR) >> 5;

    int np = g_npairs;
    if (np > MAX_PAIRS) np = MAX_PAIRS;
    const int D8 = D >> 3;           // uint4 (8 bf16) per row

    // prefetch first key
    int p_cur = gw * 8 + sub;
    unsigned pk_next = (p_cur < np) ? g_pairs[p_cur] : 0u;

    float lsum = 0.f;
    for (int p0 = gw * 8; p0 < np; p0 += nwarp * 8) {
        int p = p0 + sub;
        bool valid = p < np;
        unsigned pk = pk_next;
        // prefetch next iteration's key (head of its dependency chain)
        int p_nxt = p + nwarp * 8;
        if (p_nxt < np) pk_next = g_pairs[p_nxt];

        float d0 = 0.f, d1 = 0.f, d2 = 0.f, d3 = 0.f;
        if (valid) {
            int ij = pk >> 24;
            int n  = (pk >> 12) & 0xFFF;
            int m  = pk & 0xFFF;
            int i  = ij / B;
            int j  = ij - i * B;
            const uint4* fa = (const uint4*)(g_fbn + (size_t)(j * N + n) * D);
            const uint4* fb = (const uint4*)(g_fbn + (size_t)(i * N + m) * D);
            if (D8 == 32) {
                #pragma unroll
                for (int it = 0; it < 8; it++) {
                    int d = sl + it * 4;
                    uint4 a = fa[d], b = fb[d];
                    d0 = bfdot2(a.x, b.x, d0);   // 4 independent chains
                    d1 = bfdot2(a.y, b.y, d1);
                    d2 = bfdot2(a.z, b.z, d2);
                    d3 = bfdot2(a.w, b.w, d3);
                }
            } else {
                for (int d = sl; d < D8; d += 4) {
                    uint4 a = fa[d], b = fb[d];
                    d0 = bfdot2(a.x, b.x, d0);
                    d1 = bfdot2(a.y, b.y, d1);
                    d2 = bfdot2(a.z, b.z, d2);
                    d3 = bfdot2(a.w, b.w, d3);
                }
            }
        }
        float dot = (d0 + d1) + (d2 + d3);
        dot += __shfl_xor_sync(0xffffffffu, dot, 1);
        dot += __shfl_xor_sync(0xffffffffu, dot, 2);
        if (valid && sl == 0) lsum += 1.0f - dot;
    }
    #pragma unroll
    for (int o = 16; o; o >>= 1) lsum += __shfl_xor_sync(0xffffffffu, lsum, o);
    if (lane == 0) s_red[wid] = lsum;
    __syncthreads();
    if (wid == 0) {
        float v = (lane < 8) ? s_red[lane] : 0.f;
        #pragma unroll
        for (int o = 4; o; o >>= 1) v += __shfl_xor_sync(0xffffffffu, v, o);
        if (lane == 0 && v != 0.f) atomicAdd(&g_sum, (double)v);
    }

    // distributed reset of bucket counts for next graph replay
    {
        int ncnt = B * B * MAXC;
        for (int c = blockIdx.x * NTHR + tid; c < ncnt; c += gridDim.x * NTHR)
            g_ccnt[c] = 0;
    }

    __threadfence();
    __syncthreads();
    if (tid == 0) s_ticket = atomicAdd(&g_done, 1u);
    __syncthreads();
    if (s_ticket == gridDim.x - 1 && tid == 0) {
        __threadfence();
        double sv = atomicAdd(&g_sum, 0.0);
        int c = np < 1 ? 1 : np;
        out[0] = (float)(sv / (double)c);
        g_sum = 0.0;
        g_npairs = 0;
        g_done = 0u;
    }
}

extern "C" void kernel_launch(void* const* d_in, const int* in_sizes, int n_in,
                              void* d_out, int out_size) {
    const float* features = (const float*)d_in[0];
    const float* pts_src  = (const float*)d_in[1];
    const float* pts_dst  = (const float*)d_in[2];
    const int* hp = (const int*)d_in[4];
    const int* wp = (const int*)d_in[5];
    float* out = (float*)d_out;

    int B = in_sizes[2] / in_sizes[1];
    int N = in_sizes[1] / (2 * B);
    int D = in_sizes[0] / (B * N);
    int rows = B * N;

    int binBlocks   = (B * B * N + NTHR - 1) / NTHR;
    int matchBlocks = (B * B * N * 4 + NTHR - 1) / NTHR;
    int normBlocks  = (rows + 7) / 8;
    k_bin<<<binBlocks, NTHR>>>(pts_dst, hp, wp, B, N);
    k_mn<<<matchBlocks + normBlocks, NTHR>>>(features, pts_src, hp, wp,
                                             B, N, D, rows, matchBlocks);
    k_dot<<<DOT_GRID, NTHR>>>(out, B, N, D);
    (void)n_in; (void)out_size;
}